// round 6
// baseline (speedup 1.0000x reference)
#include <cuda_runtime.h>

// out[n, k=9*i+j, h, w] = sum_z A[n,z,h,w] * B[n,z, h+j-4, w+i-4]  (zero pad)
// N=8, Z=128, H=W=160.
//
// CTA tile TW=32 x TH=8. Threads (tx=4, h=8, j=9) = 288; warp == one j.
// Thread: 8 consecutive pixels, 9 i-shifts -> 36 packed f32x2 accumulators.
// Inner product uses fma.rn.f32x2 (2-wide fp32 FMA, PTX-only on sm_103a).
// ZC=4 z-chunks, double-buffered smem filled by cp.async.cg (zfill halo).

#define N_  8
#define Z_  128
#define H_  160
#define W_  160
#define TW  32
#define TH  8
#define ZC  4
#define NCH (Z_ / ZC)     // 32
#define AROW 36
#define BROW 44
#define BRN  16           // TH + 8
#define NT  288

__device__ __forceinline__ unsigned long long pack2(float lo, float hi) {
    unsigned long long r;
    asm("mov.b64 %0, {%1, %2};" : "=l"(r) : "f"(lo), "f"(hi));
    return r;
}
__device__ __forceinline__ void fma2(unsigned long long& d,
                                     unsigned long long a,
                                     unsigned long long b) {
    asm("fma.rn.f32x2 %0, %1, %2, %0;" : "+l"(d) : "l"(a), "l"(b));
}

__global__ __launch_bounds__(NT, 2)
void corr_kernel(const float* __restrict__ A,
                 const float* __restrict__ B,
                 float* __restrict__ out)
{
    __shared__ float As[2][ZC][TH][AROW];   // 2 * 4.5 KB
    __shared__ float Bs[2][ZC][BRN][BROW];  // 2 * 11 KB

    const int tid = threadIdx.x;
    const int tx = tid & 3;          // w = w0 + 8*tx .. +7
    const int h  = (tid >> 2) & 7;
    const int j  = tid >> 5;         // warp index

    const int w0 = blockIdx.x * TW;
    const int h0 = blockIdx.y * TH;
    const int n  = blockIdx.z;

    const size_t plane = (size_t)H_ * W_;
    const float* Abase = A + (size_t)n * Z_ * plane;
    const float* Bbase = B + (size_t)n * Z_ * plane;

    // ------- fixed fill roles -------
    // B: ZC*16*10 = 640 float4/chunk, slots s=0..2 (idx = tid + 288*s)
    unsigned boff[3];
    unsigned bsm[3];
    int      bsz[3];
    bool     bact[3];
    #pragma unroll
    for (int s = 0; s < 3; s++) {
        int idx = tid + s * NT;
        bool act = idx < ZC * BRN * 10;
        int ii = act ? idx : 0;
        int z = ii / 160;
        int rem = ii - z * 160;
        int r = rem / 10;
        int c = rem - r * 10;
        int gh = h0 - 4 + r;
        int gw = w0 - 4 + 4 * c;
        bool v = ((unsigned)gh < H_) && ((unsigned)gw <= (W_ - 4));
        bact[s] = act;
        bsz[s] = v ? 16 : 0;
        boff[s] = v ? (unsigned)(z * plane + gh * W_ + gw) : 0u;
        bsm[s] = (unsigned)__cvta_generic_to_shared(&Bs[0][z][r][4 * c]);
    }
    // A: ZC*8*8 = 256 float4/chunk (tid < 256)
    const bool aact = tid < ZC * TH * 8;
    int ai = aact ? tid : 0;
    int az = ai >> 6;
    int ar = (ai >> 3) & 7;
    int ac = ai & 7;
    const unsigned aoff = (unsigned)(az * plane + (h0 + ar) * W_ + w0 + 4 * ac);
    const unsigned asm0 = (unsigned)__cvta_generic_to_shared(&As[0][az][ar][4 * ac]);

    const unsigned BUFB = (unsigned)sizeof(Bs[0]);
    const unsigned BUFA = (unsigned)sizeof(As[0]);

    // packed accumulators: acc2[i][q] = {acc[i][2q], acc[i][2q+1]}
    unsigned long long acc2[9][4];
    #pragma unroll
    for (int i = 0; i < 9; i++)
        #pragma unroll
        for (int q = 0; q < 4; q++)
            acc2[i][q] = 0ull;

    auto issue = [&](int chunk) {
        const int buf = chunk & 1;
        const float* bsrc = Bbase + (size_t)chunk * ZC * plane;
        const float* asrc = Abase + (size_t)chunk * ZC * plane;
        const unsigned bo = buf ? BUFB : 0u;
        const unsigned ao = buf ? BUFA : 0u;
        #pragma unroll
        for (int s = 0; s < 3; s++) {
            if (bact[s]) {
                asm volatile("cp.async.cg.shared.global [%0], [%1], 16, %2;"
                             :: "r"(bsm[s] + bo), "l"(bsrc + boff[s]), "r"(bsz[s]));
            }
        }
        if (aact) {
            asm volatile("cp.async.cg.shared.global [%0], [%1], 16, 16;"
                         :: "r"(asm0 + ao), "l"(asrc + aoff));
        }
        asm volatile("cp.async.commit_group;");
    };

    issue(0);
    issue(1);

    for (int ch = 0; ch < NCH; ch++) {
        if (ch < NCH - 1) asm volatile("cp.async.wait_group 1;");
        else              asm volatile("cp.async.wait_group 0;");
        __syncthreads();

        const int buf = ch & 1;
        #pragma unroll
        for (int z = 0; z < ZC; z++) {
            const float4* ar4 = (const float4*)&As[buf][z][h][8 * tx];
            const float4 a0 = ar4[0];
            const float4 a1 = ar4[1];
            const float4* br4 = (const float4*)&Bs[buf][z][h + j][8 * tx];
            const float4 b0 = br4[0];
            const float4 b1 = br4[1];
            const float4 b2 = br4[2];
            const float4 b3 = br4[3];

            const float b[16] = {b0.x, b0.y, b0.z, b0.w, b1.x, b1.y, b1.z, b1.w,
                                 b2.x, b2.y, b2.z, b2.w, b3.x, b3.y, b3.z, b3.w};

            unsigned long long a2[4];
            a2[0] = pack2(a0.x, a0.y);
            a2[1] = pack2(a0.z, a0.w);
            a2[2] = pack2(a1.x, a1.y);
            a2[3] = pack2(a1.z, a1.w);

            // For each b-pair offset t = 2q + i: pack once, feed up to 4 FFMA2.
            #pragma unroll
            for (int t = 0; t < 15; t++) {
                const unsigned long long bt = pack2(b[t], b[t + 1]);
                #pragma unroll
                for (int q = 0; q < 4; q++) {
                    const int i = t - 2 * q;
                    if (i >= 0 && i <= 8)
                        fma2(acc2[i][q], a2[q], bt);
                }
            }
        }
        __syncthreads();

        if (ch + 2 < NCH) issue(ch + 2);
    }

    // ------- store: 18 x STG.128 -------
    float* ob = out + (((size_t)n * 81 + j) * H_ + (h0 + h)) * W_ + w0 + 8 * tx;
    #pragma unroll
    for (int i = 0; i < 9; i++) {
        float lo0, hi0, lo1, hi1;
        asm("mov.b64 {%0, %1}, %2;" : "=f"(lo0), "=f"(hi0) : "l"(acc2[i][0]));
        asm("mov.b64 {%0, %1}, %2;" : "=f"(lo1), "=f"(hi1) : "l"(acc2[i][1]));
        *(float4*)(ob + (size_t)(9 * i) * plane) = make_float4(lo0, hi0, lo1, hi1);
        asm("mov.b64 {%0, %1}, %2;" : "=f"(lo0), "=f"(hi0) : "l"(acc2[i][2]));
        asm("mov.b64 {%0, %1}, %2;" : "=f"(lo1), "=f"(hi1) : "l"(acc2[i][3]));
        *(float4*)(ob + (size_t)(9 * i) * plane + 4) = make_float4(lo0, hi0, lo1, hi1);
    }
}

extern "C" void kernel_launch(void* const* d_in, const int* in_sizes, int n_in,
                              void* d_out, int out_size)
{
    const float* imgA = (const float*)d_in[0];
    const float* imgB = (const float*)d_in[1];
    float* out = (float*)d_out;

    dim3 grid(W_ / TW, H_ / TH, N_);
    corr_kernel<<<grid, NT>>>(imgA, imgB, out);
}

// round 7
// speedup vs baseline: 2.2960x; 2.2960x over previous
#include <cuda_runtime.h>

// out[n, k=9*i+j, h, w] = sum_z A[n,z,h,w] * B[n,z, h+j-4, w+i-4]  (zero pad)
// N=8, Z=128, H=W=160.
//
// CTA tile TW=32 x TH=8. Threads (tx=4, h=8, j=9) = 288; warp == one j.
// Thread: 8 consecutive pixels, one row, 9 i-shifts -> 72 scalar accumulators.
// ZC=4 z-chunks, TRIPLE-buffered smem via cp.async.cg (zfill halo),
// single __syncthreads per chunk.

#define N_  8
#define Z_  128
#define H_  160
#define W_  160
#define TW  32
#define TH  8
#define ZC  4
#define NCH (Z_ / ZC)     // 32
#define AROW 36
#define BROW 44
#define BRN  16           // TH + 8
#define NT  288

#define ASZ (ZC * TH * AROW)      // floats per A buffer
#define BSZ (ZC * BRN * BROW)     // floats per B buffer

__global__ __launch_bounds__(NT, 2)
void corr_kernel(const float* __restrict__ A,
                 const float* __restrict__ B,
                 float* __restrict__ out)
{
    __shared__ float As[3][ZC][TH][AROW];   // 3 * 4.5 KB
    __shared__ float Bs[3][ZC][BRN][BROW];  // 3 * 11 KB   (total 46.5 KB)

    const int tid = threadIdx.x;
    const int tx = tid & 3;          // w = w0 + 8*tx .. +7
    const int h  = (tid >> 2) & 7;
    const int j  = tid >> 5;         // warp index

    const int w0 = blockIdx.x * TW;
    const int h0 = blockIdx.y * TH;
    const int n  = blockIdx.z;

    const size_t plane = (size_t)H_ * W_;
    const float* Abase = A + (size_t)n * Z_ * plane;
    const float* Bbase = B + (size_t)n * Z_ * plane;

    // ------- fixed fill roles (computed once) -------
    // B: ZC*16*10 = 640 float4/chunk, slots s=0..2 (idx = tid + 288*s)
    unsigned boff[3];
    unsigned bsm[3];
    int      bsz[3];
    bool     bact[3];
    #pragma unroll
    for (int s = 0; s < 3; s++) {
        int idx = tid + s * NT;
        bool act = idx < ZC * BRN * 10;
        int ii = act ? idx : 0;
        int z = ii / 160;
        int rem = ii - z * 160;
        int r = rem / 10;
        int c = rem - r * 10;
        int gh = h0 - 4 + r;
        int gw = w0 - 4 + 4 * c;
        bool v = ((unsigned)gh < H_) && ((unsigned)gw <= (W_ - 4));
        bact[s] = act;
        bsz[s] = v ? 16 : 0;
        boff[s] = v ? (unsigned)(z * plane + gh * W_ + gw) : 0u;
        bsm[s] = (unsigned)__cvta_generic_to_shared(&Bs[0][z][r][4 * c]);
    }
    // A: ZC*8*8 = 256 float4/chunk (tid < 256)
    const bool aact = tid < ZC * TH * 8;
    int ai = aact ? tid : 0;
    int az = ai >> 6;
    int ar = (ai >> 3) & 7;
    int ac = ai & 7;
    const unsigned aoff = (unsigned)(az * plane + (h0 + ar) * W_ + w0 + 4 * ac);
    const unsigned asm0 = (unsigned)__cvta_generic_to_shared(&As[0][az][ar][4 * ac]);

    // read-side base pointers (buffer 0)
    const float* aRd0 = &As[0][0][h][8 * tx];
    const float* bRd0 = &Bs[0][0][h + j][8 * tx];

    float acc[9][8];
    #pragma unroll
    for (int i = 0; i < 9; i++)
        #pragma unroll
        for (int p = 0; p < 8; p++)
            acc[i][p] = 0.0f;

    auto issue = [&](int chunk, int buf) {
        const float* bsrc = Bbase + (size_t)chunk * ZC * plane;
        const float* asrc = Abase + (size_t)chunk * ZC * plane;
        const unsigned bo = (unsigned)(buf * BSZ * 4);
        const unsigned ao = (unsigned)(buf * ASZ * 4);
        #pragma unroll
        for (int s = 0; s < 3; s++) {
            if (bact[s]) {
                asm volatile("cp.async.cg.shared.global [%0], [%1], 16, %2;"
                             :: "r"(bsm[s] + bo), "l"(bsrc + boff[s]), "r"(bsz[s]));
            }
        }
        if (aact) {
            asm volatile("cp.async.cg.shared.global [%0], [%1], 16, 16;"
                         :: "r"(asm0 + ao), "l"(asrc + aoff));
        }
        asm volatile("cp.async.commit_group;");
    };

    // prologue: 2 chunks in flight
    issue(0, 0);
    issue(1, 1);

    int bufc = 0;   // buffer holding chunk ch
    for (int ch = 0; ch < NCH; ch++) {
        if (ch < NCH - 1) asm volatile("cp.async.wait_group 1;");
        else              asm volatile("cp.async.wait_group 0;");
        __syncthreads();   // chunk ch visible everywhere; buf (ch+2)%3 fully drained

        // refill the freed buffer while we compute this one
        int nb = bufc + 2; if (nb >= 3) nb -= 3;
        if (ch + 2 < NCH) issue(ch + 2, nb);

        const float* aRd = aRd0 + bufc * ASZ;
        const float* bRd = bRd0 + bufc * BSZ;

        #pragma unroll
        for (int z = 0; z < ZC; z++) {
            const float4 a0 = *(const float4*)(aRd + z * (TH * AROW));
            const float4 a1 = *(const float4*)(aRd + z * (TH * AROW) + 4);
            const float4 b0 = *(const float4*)(bRd + z * (BRN * BROW));
            const float4 b1 = *(const float4*)(bRd + z * (BRN * BROW) + 4);
            const float4 b2 = *(const float4*)(bRd + z * (BRN * BROW) + 8);
            const float4 b3 = *(const float4*)(bRd + z * (BRN * BROW) + 12);

            const float a[8] = {a0.x, a0.y, a0.z, a0.w, a1.x, a1.y, a1.z, a1.w};
            const float b[16] = {b0.x, b0.y, b0.z, b0.w, b1.x, b1.y, b1.z, b1.w,
                                 b2.x, b2.y, b2.z, b2.w, b3.x, b3.y, b3.z, b3.w};

            #pragma unroll
            for (int i = 0; i < 9; i++)
                #pragma unroll
                for (int p = 0; p < 8; p++)
                    acc[i][p] += a[p] * b[p + i];
        }

        bufc = (bufc == 2) ? 0 : bufc + 1;
    }

    // ------- store: 18 x STG.128 -------
    float* ob = out + (((size_t)n * 81 + j) * H_ + (h0 + h)) * W_ + w0 + 8 * tx;
    #pragma unroll
    for (int i = 0; i < 9; i++) {
        *(float4*)(ob + (size_t)(9 * i) * plane) =
            make_float4(acc[i][0], acc[i][1], acc[i][2], acc[i][3]);
        *(float4*)(ob + (size_t)(9 * i) * plane + 4) =
            make_float4(acc[i][4], acc[i][5], acc[i][6], acc[i][7]);
    }
}

extern "C" void kernel_launch(void* const* d_in, const int* in_sizes, int n_in,
                              void* d_out, int out_size)
{
    const float* imgA = (const float*)d_in[0];
    const float* imgB = (const float*)d_in[1];
    float* out = (float*)d_out;

    dim3 grid(W_ / TW, H_ / TH, N_);
    corr_kernel<<<grid, NT>>>(imgA, imgB, out);
}